// round 8
// baseline (speedup 1.0000x reference)
#include <cuda_runtime.h>
#include <math.h>

// Problem constants
#define Bc 32
#define Nc 256
#define Tc 64
#define Mc 64
#define Hc 512
#define Wc 512
#define COL_THRESH 0.5f
#define CAND_PER_BLK 4   // candidates per block
#define BLKS_PER_B (Nc / CAND_PER_BLK)   // 64 blocks per batch

// Scratch for raw per-(b,n) scores: [f_dis, f_pg, min_col_sq, f_dac]
__device__ float4 g_scratch[Bc * Nc];
// Per-batch completion counters (zero-initialized; reset by the winner)
__device__ int g_cnt[Bc];

// ---------------------------------------------------------------------------
// Fused kernel. grid = (N/CAND_PER_BLK, B), block = 256 threads.
// Phase 1: each 64-thread group computes raw scores for one candidate.
// Phase 2: the LAST block to finish for batch b normalizes, argmaxes and
//          copies the best trajectory (threadfence-reduction pattern).
// ---------------------------------------------------------------------------
__global__ __launch_bounds__(64 * CAND_PER_BLK) void fused_kernel(
    const float* __restrict__ traj,     // (B,N,T,2)
    const float* __restrict__ goal,     // (B,2)
    const float* __restrict__ gt,       // (B,T,2)
    const float* __restrict__ obs,      // (B,M,2)
    const float* __restrict__ da,       // (B,H,W)
    float* __restrict__ out)            // [B*T*2 best | B*N scores]
{
    const int b    = blockIdx.y;
    const int tid  = threadIdx.x;
    const int c    = tid >> 6;                      // candidate slot 0..3
    const int t    = tid & 63;                      // timestep 0..63
    const int n    = blockIdx.x * CAND_PER_BLK + c; // candidate index

    __shared__ float4 s_obs[Mc];   // (-2*ox, -2*oy, |o|^2, pad)
    __shared__ float2 s_gt[Tc];
    __shared__ float  s_red[CAND_PER_BLK][3][2];
    __shared__ float  s_pg[CAND_PER_BLK];
    __shared__ int    s_last;

    // Stage transformed obstacles + gt for this batch into shared
    if (tid < Mc) {
        float2 o = ((const float2*)obs)[b * Mc + tid];
        float o2 = fmaf(o.x, o.x, o.y * o.y);
        s_obs[tid] = make_float4(-2.0f * o.x, -2.0f * o.y, o2, 0.0f);
    } else if (tid < Mc + Tc) {
        s_gt[tid - Mc] = ((const float2*)gt)[b * Tc + (tid - Mc)];
    }
    __syncthreads();

    // My trajectory point (coalesced float2 load)
    const float2 p = ((const float2*)traj)[((size_t)(b * Nc + n)) * Tc + t];

    // --- distance-to-GT term ---
    const float2 g = s_gt[t];
    float dxg = p.x - g.x, dyg = p.y - g.y;
    float dis = sqrtf(fmaf(dxg, dxg, dyg * dyg));

    // --- progress term (endpoint only) ---
    if (t == Tc - 1) {
        const float2 gl = ((const float2*)goal)[b];
        float ex = p.x - gl.x, ey = p.y - gl.y;
        s_pg[c] = sqrtf(fmaf(ex, ex, ey * ey));
    }

    // --- collision term: min over M of (|o|^2 - 2 p.o); add |p|^2 at the end
    const float BIG = 3.402823466e+38f;
    float m0 = BIG, m1 = BIG, m2 = BIG, m3 = BIG;
#pragma unroll
    for (int m = 0; m < Mc; m += 4) {
        float4 o0 = s_obs[m + 0];
        float4 o1 = s_obs[m + 1];
        float4 o2 = s_obs[m + 2];
        float4 o3 = s_obs[m + 3];
        m0 = fminf(m0, fmaf(p.y, o0.y, fmaf(p.x, o0.x, o0.z)));
        m1 = fminf(m1, fmaf(p.y, o1.y, fmaf(p.x, o1.x, o1.z)));
        m2 = fminf(m2, fmaf(p.y, o2.y, fmaf(p.x, o2.x, o2.z)));
        m3 = fminf(m3, fmaf(p.y, o3.y, fmaf(p.x, o3.x, o3.z)));
    }
    float p2 = fmaf(p.x, p.x, p.y * p.y);
    float mind2 = p2 + fminf(fminf(m0, m1), fminf(m2, m3));
    mind2 = fmaxf(mind2, 0.0f);   // guard cancellation before sqrt later

    // --- DAC term: gather from drivable mask ---
    int xi = (int)((p.x + 50.0f) / 100.0f * (float)(Wc - 1));
    int yi = (int)((p.y + 50.0f) / 100.0f * (float)(Hc - 1));
    xi = min(max(xi, 0), Wc - 1);
    yi = min(max(yi, 0), Hc - 1);
    float dac = 1.0f - __ldg(&da[(size_t)b * (Hc * Wc) + yi * Wc + xi]);

    // --- reduction within the 64-thread candidate group ---
#pragma unroll
    for (int off = 16; off > 0; off >>= 1) {
        dis   += __shfl_xor_sync(0xFFFFFFFFu, dis, off);
        dac   += __shfl_xor_sync(0xFFFFFFFFu, dac, off);
        mind2  = fminf(mind2, __shfl_xor_sync(0xFFFFFFFFu, mind2, off));
    }
    {
        const int lane1 = t & 31, w1 = t >> 5;   // warp-within-candidate: 0/1
        if (lane1 == 0) {
            s_red[c][0][w1] = dis;
            s_red[c][1][w1] = mind2;
            s_red[c][2][w1] = dac;
        }
    }
    __syncthreads();

    if (t == 0) {
        float f_dis   = (s_red[c][0][0] + s_red[c][0][1]) * (1.0f / Tc);
        float mcolsq  = fminf(s_red[c][1][0], s_red[c][1][1]);
        float f_dac   = (s_red[c][2][0] + s_red[c][2][1]) * (1.0f / Tc);
        g_scratch[b * Nc + n] = make_float4(f_dis, s_pg[c], mcolsq, f_dac);
    }
    __syncthreads();

    // ---- completion signalling: last block for this batch does the select ---
    if (tid == 0) {
        __threadfence();                      // release scratch writes
        int old = atomicAdd(&g_cnt[b], 1);
        s_last = (old == BLKS_PER_B - 1) ? 1 : 0;
    }
    __syncthreads();
    if (!s_last) return;
    __threadfence();                          // acquire others' scratch writes

    // =======================================================================
    // Phase 2 (one block per batch): normalize, combine, argmax, gather best.
    // tid = candidate index nn (0..255).
    // NOTE: block-level warp indices here (tid>>5 in 0..7), NOT the phase-1
    // candidate-group indices — that aliasing was the R5 correctness bug.
    // =======================================================================
    {
        const int nn    = tid;
        const int lane2 = tid & 31;
        const int w2    = tid >> 5;   // 0..7

        __shared__ float s_mn[8][4], s_mx[8][4];
        __shared__ float s_fmn[4], s_fmx[4];
        __shared__ float s_bs[8];
        __shared__ int   s_bi[8];
        __shared__ int   s_best;

        // L2-coherent read of all candidates' raw scores for this batch
        const float4* sc = &g_scratch[b * Nc + nn];
        float4 raw;
        raw.x = __ldcg(&sc->x);
        raw.y = __ldcg(&sc->y);
        raw.z = __ldcg(&sc->z);
        raw.w = __ldcg(&sc->w);

        float mcol = sqrtf(raw.z);
        float ttv  = mcol - COL_THRESH;
        float v[4];
        v[0] = raw.x;               // f_dis
        v[1] = raw.y;               // f_pg
        v[2] = expf(-(ttv * ttv));  // f_col
        v[3] = raw.w;               // f_dac

        // --- combined 8-value reduction (4 mins + 4 maxes) ---
        float mn4[4], mx4[4];
#pragma unroll
        for (int i = 0; i < 4; i++) { mn4[i] = v[i]; mx4[i] = v[i]; }
#pragma unroll
        for (int off = 16; off > 0; off >>= 1) {
#pragma unroll
            for (int i = 0; i < 4; i++) {
                mn4[i] = fminf(mn4[i], __shfl_xor_sync(0xFFFFFFFFu, mn4[i], off));
                mx4[i] = fmaxf(mx4[i], __shfl_xor_sync(0xFFFFFFFFu, mx4[i], off));
            }
        }
        if (lane2 == 0) {
#pragma unroll
            for (int i = 0; i < 4; i++) { s_mn[w2][i] = mn4[i]; s_mx[w2][i] = mx4[i]; }
        }
        __syncthreads();
        if (w2 == 0) {   // full warp participates — convergent shuffles
#pragma unroll
            for (int i = 0; i < 4; i++) {
                mn4[i] = s_mn[lane2 & 7][i];
                mx4[i] = s_mx[lane2 & 7][i];
            }
#pragma unroll
            for (int off = 4; off > 0; off >>= 1) {
#pragma unroll
                for (int i = 0; i < 4; i++) {
                    mn4[i] = fminf(mn4[i], __shfl_xor_sync(0xFFFFFFFFu, mn4[i], off));
                    mx4[i] = fmaxf(mx4[i], __shfl_xor_sync(0xFFFFFFFFu, mx4[i], off));
                }
            }
            if (lane2 == 0) {
#pragma unroll
                for (int i = 0; i < 4; i++) { s_fmn[i] = mn4[i]; s_fmx[i] = mx4[i]; }
            }
        }
        __syncthreads();

        float score = 0.0f;
#pragma unroll
        for (int i = 0; i < 4; i++) {
            float d = s_fmx[i] - s_fmn[i];
            d = (d == 0.0f) ? 1.0f : d;
            score += (v[i] - s_fmn[i]) / d;
        }
        score = -score;

        // scores output region follows the best_trajectory block
        float* out_scores = out + (Bc * Tc * 2);
        out_scores[b * Nc + nn] = score;

        // --- argmax with first-index tie-break (matches jnp.argmax) ---
        float bs = score;
        int   bi = nn;
#pragma unroll
        for (int off = 16; off > 0; off >>= 1) {
            float os = __shfl_xor_sync(0xFFFFFFFFu, bs, off);
            int   oi = __shfl_xor_sync(0xFFFFFFFFu, bi, off);
            if (os > bs || (os == bs && oi < bi)) { bs = os; bi = oi; }
        }
        if (lane2 == 0) { s_bs[w2] = bs; s_bi[w2] = bi; }
        __syncthreads();
        if (w2 == 0) {   // full warp participates — convergent shuffles
            bs = s_bs[lane2 & 7];
            bi = s_bi[lane2 & 7];
#pragma unroll
            for (int off = 4; off > 0; off >>= 1) {
                float os = __shfl_xor_sync(0xFFFFFFFFu, bs, off);
                int   oi = __shfl_xor_sync(0xFFFFFFFFu, bi, off);
                if (os > bs || (os == bs && oi < bi)) { bs = os; bi = oi; }
            }
            if (lane2 == 0) s_best = bi;
        }
        __syncthreads();

        // --- copy best trajectory: T*2 = 128 floats = 64 float2 ---
        const int best = s_best;
        if (nn < Tc) {
            ((float2*)out)[b * Tc + nn] =
                ((const float2*)traj)[((size_t)(b * Nc + best)) * Tc + nn];
        }

        // reset counter for the next graph replay (all arrivals already in)
        if (tid == 0) g_cnt[b] = 0;
    }
}

// ---------------------------------------------------------------------------
// Launch
// ---------------------------------------------------------------------------
extern "C" void kernel_launch(void* const* d_in, const int* in_sizes, int n_in,
                              void* d_out, int out_size)
{
    const float* traj = (const float*)d_in[0];   // (B,N,T,2)
    const float* goal = (const float*)d_in[1];   // (B,2)
    const float* gt   = (const float*)d_in[2];   // (B,T,2)
    const float* obs  = (const float*)d_in[3];   // (B,M,2)
    const float* da   = (const float*)d_in[4];   // (B,H,W)
    float* out = (float*)d_out;

    dim3 g1(BLKS_PER_B, Bc);
    fused_kernel<<<g1, 64 * CAND_PER_BLK>>>(traj, goal, gt, obs, da, out);
}

// round 11
// speedup vs baseline: 1.2226x; 1.2226x over previous
#include <cuda_runtime.h>
#include <math.h>

// Problem constants
#define Bc 32
#define Nc 256
#define Tc 64
#define Mc 64
#define Hc 512
#define Wc 512
#define COL_THRESH 0.5f

#define GRP 16                      // threads per candidate
#define T_PER_THR 4                 // timesteps per thread (GRP*T_PER_THR = Tc)
#define CAND_PER_BLK 16             // candidates per 256-thread block
#define BLKS_PER_B (Nc / CAND_PER_BLK)   // 16 blocks per batch

// Scratch for raw per-(b,n) scores: [f_dis, f_pg, min_col_sq, f_dac]
__device__ float4 g_scratch[Bc * Nc];
// Per-batch completion counters (zero-initialized; reset by the winner)
__device__ int g_cnt[Bc];

// ---------------------------------------------------------------------------
// Fused kernel. grid = (16, B), block = 256 threads — SINGLE WAVE (512 blocks).
// Phase 1: 16-thread groups compute raw scores, 4 timesteps per thread.
// Phase 2: the LAST block per batch normalizes, argmaxes, copies best traj.
// ---------------------------------------------------------------------------
__global__ __launch_bounds__(256) void fused_kernel(
    const float* __restrict__ traj,     // (B,N,T,2)
    const float* __restrict__ goal,     // (B,2)
    const float* __restrict__ gt,       // (B,T,2)
    const float* __restrict__ obs,      // (B,M,2)
    const float* __restrict__ da,       // (B,H,W)
    float* __restrict__ out)            // [B*T*2 best | B*N scores]
{
    const int b   = blockIdx.y;
    const int tid = threadIdx.x;
    const int c   = tid >> 4;                       // candidate slot 0..15
    const int tg  = tid & 15;                       // thread-in-group 0..15
    const int n   = blockIdx.x * CAND_PER_BLK + c;  // candidate index
    const int t0  = tg * T_PER_THR;                 // first timestep

    __shared__ float4 s_obs[Mc];   // (-2*ox, -2*oy, |o|^2, pad)
    __shared__ int    s_last;

    // Stage transformed obstacles for this batch into shared
    if (tid < Mc) {
        float2 o = ((const float2*)obs)[b * Mc + tid];
        float o2 = fmaf(o.x, o.x, o.y * o.y);
        s_obs[tid] = make_float4(-2.0f * o.x, -2.0f * o.y, o2, 0.0f);
    }
    __syncthreads();

    // --- load my 4 trajectory points (2x float4, coalesced) ---
    const float4* traj4 = (const float4*)traj;
    const int base4 = ((b * Nc + n) * Tc + t0) >> 1;
    float4 q0 = traj4[base4];
    float4 q1 = traj4[base4 + 1];
    float px[4] = {q0.x, q0.z, q1.x, q1.z};
    float py[4] = {q0.y, q0.w, q1.y, q1.w};

    // --- distance-to-GT: 4 points ---
    const float4* gt4 = (const float4*)gt;
    const int gbase4 = (b * Tc + t0) >> 1;
    float4 G0 = __ldg(&gt4[gbase4]);
    float4 G1 = __ldg(&gt4[gbase4 + 1]);
    float gx[4] = {G0.x, G0.z, G1.x, G1.z};
    float gy[4] = {G0.y, G0.w, G1.y, G1.w};

    float dis = 0.0f;
#pragma unroll
    for (int j = 0; j < 4; j++) {
        float dx = px[j] - gx[j], dy = py[j] - gy[j];
        dis += sqrtf(fmaf(dx, dx, dy * dy));
    }

    // --- progress term: only the thread owning t=63 contributes (summed) ---
    float pg = 0.0f;
    if (tg == GRP - 1) {
        float2 gl = ((const float2*)goal)[b];
        float ex = px[3] - gl.x, ey = py[3] - gl.y;
        pg = sqrtf(fmaf(ex, ex, ey * ey));
    }

    // --- collision: min over M of (|o|^2 - 2 p.o) per point; 1 LDS / 4 pts ---
    const float BIG = 3.402823466e+38f;
    float mc[4] = {BIG, BIG, BIG, BIG};
#pragma unroll 8
    for (int m = 0; m < Mc; m++) {
        float4 o = s_obs[m];       // broadcast, conflict-free
#pragma unroll
        for (int j = 0; j < 4; j++)
            mc[j] = fminf(mc[j], fmaf(py[j], o.y, fmaf(px[j], o.x, o.z)));
    }
    float mind2 = BIG;
#pragma unroll
    for (int j = 0; j < 4; j++)
        mind2 = fminf(mind2, fmaf(px[j], px[j], py[j] * py[j]) + mc[j]);
    mind2 = fmaxf(mind2, 0.0f);    // clamp commutes with min; guard sqrt later

    // --- DAC: 4 independent gathers ---
    float dac = 0.0f;
#pragma unroll
    for (int j = 0; j < 4; j++) {
        int xi = (int)((px[j] + 50.0f) / 100.0f * (float)(Wc - 1));
        int yi = (int)((py[j] + 50.0f) / 100.0f * (float)(Hc - 1));
        xi = min(max(xi, 0), Wc - 1);
        yi = min(max(yi, 0), Hc - 1);
        dac += 1.0f - __ldg(&da[(size_t)b * (Hc * Wc) + yi * Wc + xi]);
    }

    // --- 16-lane group reduction (xor offsets stay inside the group) ---
#pragma unroll
    for (int off = 8; off > 0; off >>= 1) {
        dis   += __shfl_xor_sync(0xFFFFFFFFu, dis, off);
        dac   += __shfl_xor_sync(0xFFFFFFFFu, dac, off);
        pg    += __shfl_xor_sync(0xFFFFFFFFu, pg, off);
        mind2  = fminf(mind2, __shfl_xor_sync(0xFFFFFFFFu, mind2, off));
    }
    if (tg == 0) {
        g_scratch[b * Nc + n] =
            make_float4(dis * (1.0f / Tc), pg, mind2, dac * (1.0f / Tc));
        // storer fences its own write; __syncthreads below orders it before
        // the block's completion atomic (fence by non-storers is useless work)
        __threadfence();
    }
    __syncthreads();

    // ---- completion signalling: last block for this batch does the select ---
    if (tid == 0) {
        int old = atomicAdd(&g_cnt[b], 1);
        s_last = (old == BLKS_PER_B - 1) ? 1 : 0;
    }
    __syncthreads();
    if (!s_last) return;
    __threadfence();                          // acquire others' scratch writes

    // =======================================================================
    // Phase 2 (one block per batch): normalize, combine, argmax, gather best.
    // tid = candidate index nn (0..255); block-level warp indices.
    // =======================================================================
    {
        const int nn    = tid;
        const int lane2 = tid & 31;
        const int w2    = tid >> 5;   // 0..7

        __shared__ float s_mn[8][4], s_mx[8][4];
        __shared__ float s_fmn[4], s_fmx[4];
        __shared__ float s_bs[8];
        __shared__ int   s_bi[8];
        __shared__ int   s_best;

        // L2-coherent read of all candidates' raw scores for this batch
        const float4* sc = &g_scratch[b * Nc + nn];
        float4 raw;
        raw.x = __ldcg(&sc->x);
        raw.y = __ldcg(&sc->y);
        raw.z = __ldcg(&sc->z);
        raw.w = __ldcg(&sc->w);

        float mcol = sqrtf(raw.z);
        float ttv  = mcol - COL_THRESH;
        float v[4];
        v[0] = raw.x;               // f_dis
        v[1] = raw.y;               // f_pg
        v[2] = expf(-(ttv * ttv));  // f_col
        v[3] = raw.w;               // f_dac

        // --- combined 8-value reduction (4 mins + 4 maxes) ---
        float mn4[4], mx4[4];
#pragma unroll
        for (int i = 0; i < 4; i++) { mn4[i] = v[i]; mx4[i] = v[i]; }
#pragma unroll
        for (int off = 16; off > 0; off >>= 1) {
#pragma unroll
            for (int i = 0; i < 4; i++) {
                mn4[i] = fminf(mn4[i], __shfl_xor_sync(0xFFFFFFFFu, mn4[i], off));
                mx4[i] = fmaxf(mx4[i], __shfl_xor_sync(0xFFFFFFFFu, mx4[i], off));
            }
        }
        if (lane2 == 0) {
#pragma unroll
            for (int i = 0; i < 4; i++) { s_mn[w2][i] = mn4[i]; s_mx[w2][i] = mx4[i]; }
        }
        __syncthreads();
        if (w2 == 0) {   // full warp participates — convergent shuffles
#pragma unroll
            for (int i = 0; i < 4; i++) {
                mn4[i] = s_mn[lane2 & 7][i];
                mx4[i] = s_mx[lane2 & 7][i];
            }
#pragma unroll
            for (int off = 4; off > 0; off >>= 1) {
#pragma unroll
                for (int i = 0; i < 4; i++) {
                    mn4[i] = fminf(mn4[i], __shfl_xor_sync(0xFFFFFFFFu, mn4[i], off));
                    mx4[i] = fmaxf(mx4[i], __shfl_xor_sync(0xFFFFFFFFu, mx4[i], off));
                }
            }
            if (lane2 == 0) {
#pragma unroll
                for (int i = 0; i < 4; i++) { s_fmn[i] = mn4[i]; s_fmx[i] = mx4[i]; }
            }
        }
        __syncthreads();

        float score = 0.0f;
#pragma unroll
        for (int i = 0; i < 4; i++) {
            float d = s_fmx[i] - s_fmn[i];
            d = (d == 0.0f) ? 1.0f : d;
            score += (v[i] - s_fmn[i]) / d;
        }
        score = -score;

        // scores output region follows the best_trajectory block
        float* out_scores = out + (Bc * Tc * 2);
        out_scores[b * Nc + nn] = score;

        // --- argmax with first-index tie-break (matches jnp.argmax) ---
        float bs = score;
        int   bi = nn;
#pragma unroll
        for (int off = 16; off > 0; off >>= 1) {
            float os = __shfl_xor_sync(0xFFFFFFFFu, bs, off);
            int   oi = __shfl_xor_sync(0xFFFFFFFFu, bi, off);
            if (os > bs || (os == bs && oi < bi)) { bs = os; bi = oi; }
        }
        if (lane2 == 0) { s_bs[w2] = bs; s_bi[w2] = bi; }
        __syncthreads();
        if (w2 == 0) {   // full warp participates — convergent shuffles
            bs = s_bs[lane2 & 7];
            bi = s_bi[lane2 & 7];
#pragma unroll
            for (int off = 4; off > 0; off >>= 1) {
                float os = __shfl_xor_sync(0xFFFFFFFFu, bs, off);
                int   oi = __shfl_xor_sync(0xFFFFFFFFu, bi, off);
                if (os > bs || (os == bs && oi < bi)) { bs = os; bi = oi; }
            }
            if (lane2 == 0) s_best = bi;
        }
        __syncthreads();

        // --- copy best trajectory: T*2 = 128 floats = 64 float2 ---
        const int best = s_best;
        if (nn < Tc) {
            ((float2*)out)[b * Tc + nn] =
                ((const float2*)traj)[((size_t)(b * Nc + best)) * Tc + nn];
        }

        // reset counter for the next graph replay (all arrivals already in)
        if (tid == 0) g_cnt[b] = 0;
    }
}

// ---------------------------------------------------------------------------
// Launch
// ---------------------------------------------------------------------------
extern "C" void kernel_launch(void* const* d_in, const int* in_sizes, int n_in,
                              void* d_out, int out_size)
{
    const float* traj = (const float*)d_in[0];   // (B,N,T,2)
    const float* goal = (const float*)d_in[1];   // (B,2)
    const float* gt   = (const float*)d_in[2];   // (B,T,2)
    const float* obs  = (const float*)d_in[3];   // (B,M,2)
    const float* da   = (const float*)d_in[4];   // (B,H,W)
    float* out = (float*)d_out;

    dim3 g1(BLKS_PER_B, Bc);
    fused_kernel<<<g1, 256>>>(traj, goal, gt, obs, da, out);
}

// round 12
// speedup vs baseline: 1.2343x; 1.0095x over previous
#include <cuda_runtime.h>
#include <math.h>

// Problem constants
#define Bc 32
#define Nc 256
#define Tc 64
#define Mc 64
#define Hc 512
#define Wc 512
#define COL_THRESH 0.5f

#define GRP 16                      // threads per candidate
#define T_PER_THR 4                 // timesteps per thread (GRP*T_PER_THR = Tc)
#define CAND_PER_BLK 16             // candidates per 256-thread block
#define BLKS_PER_B (Nc / CAND_PER_BLK)   // 16 blocks per batch

// Scratch for raw per-(b,n) scores: [f_dis, f_pg, min_col_sq, f_dac]
__device__ float4 g_scratch[Bc * Nc];
// Per-batch completion counters (zero-initialized; reset by the winner)
__device__ int g_cnt[Bc];

// ---------------------------------------------------------------------------
// Fused kernel. grid = (16, B), block = 256 threads — SINGLE WAVE (512 blocks).
// Phase 1: 16-thread groups compute raw scores, 4 timesteps per thread.
//          Loads are front-batched so DRAM latency overlaps compute.
// Phase 2: the LAST block per batch normalizes, argmaxes, copies best traj.
// ---------------------------------------------------------------------------
__global__ __launch_bounds__(256) void fused_kernel(
    const float* __restrict__ traj,     // (B,N,T,2)
    const float* __restrict__ goal,     // (B,2)
    const float* __restrict__ gt,       // (B,T,2)
    const float* __restrict__ obs,      // (B,M,2)
    const float* __restrict__ da,       // (B,H,W)
    float* __restrict__ out)            // [B*T*2 best | B*N scores]
{
    const int b   = blockIdx.y;
    const int tid = threadIdx.x;
    const int c   = tid >> 4;                       // candidate slot 0..15
    const int tg  = tid & 15;                       // thread-in-group 0..15
    const int n   = blockIdx.x * CAND_PER_BLK + c;  // candidate index
    const int t0  = tg * T_PER_THR;                 // first timestep

    __shared__ float4 s_obs[Mc];   // (-2*ox, -2*oy, |o|^2, pad)
    __shared__ int    s_last;

    // ===== FRONT-BATCHED LOADS: all independent DRAM requests first =====

    // my 4 trajectory points (2x float4, coalesced)
    const float4* traj4 = (const float4*)traj;
    const int base4 = ((b * Nc + n) * Tc + t0) >> 1;
    float4 q0 = traj4[base4];
    float4 q1 = traj4[base4 + 1];

    // gt points (broadcast within batch; L1/L2 resident after first block)
    const float4* gt4 = (const float4*)gt;
    const int gbase4 = (b * Tc + t0) >> 1;
    float4 G0 = __ldg(&gt4[gbase4]);
    float4 G1 = __ldg(&gt4[gbase4 + 1]);

    // goal (only last group thread needs it)
    float2 gl = make_float2(0.0f, 0.0f);
    if (tg == GRP - 1) gl = ((const float2*)goal)[b];

    // obstacle prefetch into registers (2 warps' worth of threads)
    float2 opre = make_float2(0.0f, 0.0f);
    if (tid < Mc) opre = ((const float2*)obs)[b * Mc + tid];

    // unpack points
    float px[4] = {q0.x, q0.z, q1.x, q1.z};
    float py[4] = {q0.y, q0.w, q1.y, q1.w};

    // ===== DAC gathers issued NOW so DRAM latency hides under the loop =====
    float dval[4];
#pragma unroll
    for (int j = 0; j < 4; j++) {
        int xi = (int)((px[j] + 50.0f) / 100.0f * (float)(Wc - 1));
        int yi = (int)((py[j] + 50.0f) / 100.0f * (float)(Hc - 1));
        xi = min(max(xi, 0), Wc - 1);
        yi = min(max(yi, 0), Hc - 1);
        dval[j] = __ldg(&da[(size_t)b * (Hc * Wc) + yi * Wc + xi]);
    }

    // stage transformed obstacles (prefetched) into shared
    if (tid < Mc) {
        float o2 = fmaf(opre.x, opre.x, opre.y * opre.y);
        s_obs[tid] = make_float4(-2.0f * opre.x, -2.0f * opre.y, o2, 0.0f);
    }

    // --- distance-to-GT while the STS drains ---
    float gx[4] = {G0.x, G0.z, G1.x, G1.z};
    float gy[4] = {G0.y, G0.w, G1.y, G1.w};
    float dis = 0.0f;
#pragma unroll
    for (int j = 0; j < 4; j++) {
        float dx = px[j] - gx[j], dy = py[j] - gy[j];
        dis += sqrtf(fmaf(dx, dx, dy * dy));
    }

    // --- progress term (endpoint owner only) ---
    float pg = 0.0f;
    if (tg == GRP - 1) {
        float ex = px[3] - gl.x, ey = py[3] - gl.y;
        pg = sqrtf(fmaf(ex, ex, ey * ey));
    }

    __syncthreads();   // obstacles visible

    // --- collision: min over M of (|o|^2 - 2 p.o) per point; 1 LDS / 4 pts ---
    const float BIG = 3.402823466e+38f;
    float mc[4] = {BIG, BIG, BIG, BIG};
#pragma unroll 8
    for (int m = 0; m < Mc; m++) {
        float4 o = s_obs[m];       // broadcast, conflict-free
#pragma unroll
        for (int j = 0; j < 4; j++)
            mc[j] = fminf(mc[j], fmaf(py[j], o.y, fmaf(px[j], o.x, o.z)));
    }
    float mind2 = BIG;
#pragma unroll
    for (int j = 0; j < 4; j++)
        mind2 = fminf(mind2, fmaf(px[j], px[j], py[j] * py[j]) + mc[j]);
    mind2 = fmaxf(mind2, 0.0f);    // clamp commutes with min; guard sqrt later

    // --- consume DAC gathers (long since landed) ---
    float dac = 0.0f;
#pragma unroll
    for (int j = 0; j < 4; j++) dac += 1.0f - dval[j];

    // --- 16-lane group reduction (xor offsets stay inside the group) ---
#pragma unroll
    for (int off = 8; off > 0; off >>= 1) {
        dis   += __shfl_xor_sync(0xFFFFFFFFu, dis, off);
        dac   += __shfl_xor_sync(0xFFFFFFFFu, dac, off);
        pg    += __shfl_xor_sync(0xFFFFFFFFu, pg, off);
        mind2  = fminf(mind2, __shfl_xor_sync(0xFFFFFFFFu, mind2, off));
    }
    if (tg == 0) {
        g_scratch[b * Nc + n] =
            make_float4(dis * (1.0f / Tc), pg, mind2, dac * (1.0f / Tc));
        __threadfence();   // storer fences its own write before block signal
    }
    __syncthreads();

    // ---- completion signalling: last block for this batch does the select ---
    if (tid == 0) {
        int old = atomicAdd(&g_cnt[b], 1);
        s_last = (old == BLKS_PER_B - 1) ? 1 : 0;
    }
    __syncthreads();
    if (!s_last) return;
    __threadfence();                          // acquire others' scratch writes

    // =======================================================================
    // Phase 2 (one block per batch): normalize, combine, argmax, gather best.
    // tid = candidate index nn (0..255); block-level warp indices.
    // =======================================================================
    {
        const int nn    = tid;
        const int lane2 = tid & 31;
        const int w2    = tid >> 5;   // 0..7

        __shared__ float s_mn[8][4], s_mx[8][4];
        __shared__ float s_fmn[4], s_fmx[4];
        __shared__ float s_bs[8];
        __shared__ int   s_bi[8];
        __shared__ int   s_best;

        // L2-coherent read of all candidates' raw scores for this batch
        const float4* sc = &g_scratch[b * Nc + nn];
        float4 raw;
        raw.x = __ldcg(&sc->x);
        raw.y = __ldcg(&sc->y);
        raw.z = __ldcg(&sc->z);
        raw.w = __ldcg(&sc->w);

        float mcol = sqrtf(raw.z);
        float ttv  = mcol - COL_THRESH;
        float v[4];
        v[0] = raw.x;               // f_dis
        v[1] = raw.y;               // f_pg
        v[2] = expf(-(ttv * ttv));  // f_col
        v[3] = raw.w;               // f_dac

        // --- combined 8-value reduction (4 mins + 4 maxes) ---
        float mn4[4], mx4[4];
#pragma unroll
        for (int i = 0; i < 4; i++) { mn4[i] = v[i]; mx4[i] = v[i]; }
#pragma unroll
        for (int off = 16; off > 0; off >>= 1) {
#pragma unroll
            for (int i = 0; i < 4; i++) {
                mn4[i] = fminf(mn4[i], __shfl_xor_sync(0xFFFFFFFFu, mn4[i], off));
                mx4[i] = fmaxf(mx4[i], __shfl_xor_sync(0xFFFFFFFFu, mx4[i], off));
            }
        }
        if (lane2 == 0) {
#pragma unroll
            for (int i = 0; i < 4; i++) { s_mn[w2][i] = mn4[i]; s_mx[w2][i] = mx4[i]; }
        }
        __syncthreads();
        if (w2 == 0) {   // full warp participates — convergent shuffles
#pragma unroll
            for (int i = 0; i < 4; i++) {
                mn4[i] = s_mn[lane2 & 7][i];
                mx4[i] = s_mx[lane2 & 7][i];
            }
#pragma unroll
            for (int off = 4; off > 0; off >>= 1) {
#pragma unroll
                for (int i = 0; i < 4; i++) {
                    mn4[i] = fminf(mn4[i], __shfl_xor_sync(0xFFFFFFFFu, mn4[i], off));
                    mx4[i] = fmaxf(mx4[i], __shfl_xor_sync(0xFFFFFFFFu, mx4[i], off));
                }
            }
            if (lane2 == 0) {
#pragma unroll
                for (int i = 0; i < 4; i++) { s_fmn[i] = mn4[i]; s_fmx[i] = mx4[i]; }
            }
        }
        __syncthreads();

        float score = 0.0f;
#pragma unroll
        for (int i = 0; i < 4; i++) {
            float d = s_fmx[i] - s_fmn[i];
            d = (d == 0.0f) ? 1.0f : d;
            score += (v[i] - s_fmn[i]) / d;
        }
        score = -score;

        // scores output region follows the best_trajectory block
        float* out_scores = out + (Bc * Tc * 2);
        out_scores[b * Nc + nn] = score;

        // --- argmax with first-index tie-break (matches jnp.argmax) ---
        float bs = score;
        int   bi = nn;
#pragma unroll
        for (int off = 16; off > 0; off >>= 1) {
            float os = __shfl_xor_sync(0xFFFFFFFFu, bs, off);
            int   oi = __shfl_xor_sync(0xFFFFFFFFu, bi, off);
            if (os > bs || (os == bs && oi < bi)) { bs = os; bi = oi; }
        }
        if (lane2 == 0) { s_bs[w2] = bs; s_bi[w2] = bi; }
        __syncthreads();
        if (w2 == 0) {   // full warp participates — convergent shuffles
            bs = s_bs[lane2 & 7];
            bi = s_bi[lane2 & 7];
#pragma unroll
            for (int off = 4; off > 0; off >>= 1) {
                float os = __shfl_xor_sync(0xFFFFFFFFu, bs, off);
                int   oi = __shfl_xor_sync(0xFFFFFFFFu, bi, off);
                if (os > bs || (os == bs && oi < bi)) { bs = os; bi = oi; }
            }
            if (lane2 == 0) s_best = bi;
        }
        __syncthreads();

        // --- copy best trajectory: T*2 = 128 floats = 64 float2 ---
        const int best = s_best;
        if (nn < Tc) {
            ((float2*)out)[b * Tc + nn] =
                ((const float2*)traj)[((size_t)(b * Nc + best)) * Tc + nn];
        }

        // reset counter for the next graph replay (all arrivals already in)
        if (tid == 0) g_cnt[b] = 0;
    }
}

// ---------------------------------------------------------------------------
// Launch
// ---------------------------------------------------------------------------
extern "C" void kernel_launch(void* const* d_in, const int* in_sizes, int n_in,
                              void* d_out, int out_size)
{
    const float* traj = (const float*)d_in[0];   // (B,N,T,2)
    const float* goal = (const float*)d_in[1];   // (B,2)
    const float* gt   = (const float*)d_in[2];   // (B,T,2)
    const float* obs  = (const float*)d_in[3];   // (B,M,2)
    const float* da   = (const float*)d_in[4];   // (B,H,W)
    float* out = (float*)d_out;

    dim3 g1(BLKS_PER_B, Bc);
    fused_kernel<<<g1, 256>>>(traj, goal, gt, obs, da, out);
}

// round 13
// speedup vs baseline: 1.2414x; 1.0057x over previous
#include <cuda_runtime.h>
#include <math.h>

// Problem constants
#define Bc 32
#define Nc 256
#define Tc 64
#define Mc 64
#define Hc 512
#define Wc 512
#define COL_THRESH 0.5f

#define GRP 8                       // threads per candidate
#define T_PER_THR 8                 // timesteps per thread (GRP*T_PER_THR = Tc)
#define CAND_PER_BLK 16             // candidates per 128-thread block
#define THREADS 128
#define BLKS_PER_B (Nc / CAND_PER_BLK)   // 16 blocks per batch -> 512 blocks

// Scratch for raw per-(b,n) scores: [f_dis, f_pg, min_col_sq, f_dac]
__device__ float4 g_scratch[Bc * Nc];
// Per-batch completion counters (zero-initialized; reset by the winner)
__device__ int g_cnt[Bc];

// ---------------------------------------------------------------------------
// Fused kernel. grid = (16, B), block = 128 threads — 512 blocks, one wave.
// Phase 1: 8-thread groups compute raw scores, 8 timesteps per thread
//          (pair math at ~3.1 issue slots per point-obstacle pair).
// Phase 2: the LAST block per batch normalizes, argmaxes, copies best traj
//          (2 candidates per thread).
// ---------------------------------------------------------------------------
__global__ __launch_bounds__(THREADS) void fused_kernel(
    const float* __restrict__ traj,     // (B,N,T,2)
    const float* __restrict__ goal,     // (B,2)
    const float* __restrict__ gt,       // (B,T,2)
    const float* __restrict__ obs,      // (B,M,2)
    const float* __restrict__ da,       // (B,H,W)
    float* __restrict__ out)            // [B*T*2 best | B*N scores]
{
    const int b   = blockIdx.y;
    const int tid = threadIdx.x;
    const int c   = tid >> 3;                       // candidate slot 0..15
    const int tg  = tid & 7;                        // thread-in-group 0..7
    const int n   = blockIdx.x * CAND_PER_BLK + c;  // candidate index
    const int t0  = tg * T_PER_THR;                 // first timestep

    __shared__ float4 s_obs[Mc];   // (-2*ox, -2*oy, |o|^2, pad)
    __shared__ int    s_last;

    // ===== FRONT-BATCHED LOADS =====

    // my 8 trajectory points (4x float4, coalesced)
    const float4* traj4 = (const float4*)traj;
    const int base4 = ((b * Nc + n) * Tc + t0) >> 1;
    float4 q0 = traj4[base4];
    float4 q1 = traj4[base4 + 1];
    float4 q2 = traj4[base4 + 2];
    float4 q3 = traj4[base4 + 3];

    // gt points (batch-broadcast, cached)
    const float4* gt4 = (const float4*)gt;
    const int gbase4 = (b * Tc + t0) >> 1;
    float4 G0 = __ldg(&gt4[gbase4]);
    float4 G1 = __ldg(&gt4[gbase4 + 1]);
    float4 G2 = __ldg(&gt4[gbase4 + 2]);
    float4 G3 = __ldg(&gt4[gbase4 + 3]);

    // goal (endpoint-owner only)
    float2 gl = make_float2(0.0f, 0.0f);
    if (tg == GRP - 1) gl = ((const float2*)goal)[b];

    // obstacle prefetch into registers (first 64 threads)
    float2 opre = make_float2(0.0f, 0.0f);
    if (tid < Mc) opre = ((const float2*)obs)[b * Mc + tid];

    // unpack points
    float px[8] = {q0.x, q0.z, q1.x, q1.z, q2.x, q2.z, q3.x, q3.z};
    float py[8] = {q0.y, q0.w, q1.y, q1.w, q2.y, q2.w, q3.y, q3.w};

    // ===== DAC gathers issued early so DRAM latency hides under the loop =====
    float dval[8];
#pragma unroll
    for (int j = 0; j < 8; j++) {
        int xi = (int)((px[j] + 50.0f) / 100.0f * (float)(Wc - 1));
        int yi = (int)((py[j] + 50.0f) / 100.0f * (float)(Hc - 1));
        xi = min(max(xi, 0), Wc - 1);
        yi = min(max(yi, 0), Hc - 1);
        dval[j] = __ldg(&da[(size_t)b * (Hc * Wc) + yi * Wc + xi]);
    }

    // stage transformed obstacles into shared
    if (tid < Mc) {
        float o2 = fmaf(opre.x, opre.x, opre.y * opre.y);
        s_obs[tid] = make_float4(-2.0f * opre.x, -2.0f * opre.y, o2, 0.0f);
    }

    // --- distance-to-GT while the STS drains ---
    float gx[8] = {G0.x, G0.z, G1.x, G1.z, G2.x, G2.z, G3.x, G3.z};
    float gy[8] = {G0.y, G0.w, G1.y, G1.w, G2.y, G2.w, G3.y, G3.w};
    float dis = 0.0f;
#pragma unroll
    for (int j = 0; j < 8; j++) {
        float dx = px[j] - gx[j], dy = py[j] - gy[j];
        dis += sqrtf(fmaf(dx, dx, dy * dy));
    }

    // --- progress term (endpoint owner only) ---
    float pg = 0.0f;
    if (tg == GRP - 1) {
        float ex = px[7] - gl.x, ey = py[7] - gl.y;
        pg = sqrtf(fmaf(ex, ex, ey * ey));
    }

    __syncthreads();   // obstacles visible

    // --- collision: min over M of (|o|^2 - 2 p.o) per point; 1 LDS / 8 pts ---
    const float BIG = 3.402823466e+38f;
    float mc[8] = {BIG, BIG, BIG, BIG, BIG, BIG, BIG, BIG};
#pragma unroll 4
    for (int m = 0; m < Mc; m++) {
        float4 o = s_obs[m];       // broadcast, conflict-free
#pragma unroll
        for (int j = 0; j < 8; j++)
            mc[j] = fminf(mc[j], fmaf(py[j], o.y, fmaf(px[j], o.x, o.z)));
    }
    float mind2 = BIG;
#pragma unroll
    for (int j = 0; j < 8; j++)
        mind2 = fminf(mind2, fmaf(px[j], px[j], py[j] * py[j]) + mc[j]);
    mind2 = fmaxf(mind2, 0.0f);    // clamp commutes with min; guard sqrt later

    // --- consume DAC gathers (long since landed) ---
    float dac = 0.0f;
#pragma unroll
    for (int j = 0; j < 8; j++) dac += 1.0f - dval[j];

    // --- 8-lane group reduction (xor offsets stay inside the group) ---
#pragma unroll
    for (int off = 4; off > 0; off >>= 1) {
        dis   += __shfl_xor_sync(0xFFFFFFFFu, dis, off);
        dac   += __shfl_xor_sync(0xFFFFFFFFu, dac, off);
        pg    += __shfl_xor_sync(0xFFFFFFFFu, pg, off);
        mind2  = fminf(mind2, __shfl_xor_sync(0xFFFFFFFFu, mind2, off));
    }
    if (tg == 0) {
        g_scratch[b * Nc + n] =
            make_float4(dis * (1.0f / Tc), pg, mind2, dac * (1.0f / Tc));
        __threadfence();   // storer fences its own write before block signal
    }
    __syncthreads();

    // ---- completion signalling: last block for this batch does the select ---
    if (tid == 0) {
        int old = atomicAdd(&g_cnt[b], 1);
        s_last = (old == BLKS_PER_B - 1) ? 1 : 0;
    }
    __syncthreads();
    if (!s_last) return;
    __threadfence();                          // acquire others' scratch writes

    // =======================================================================
    // Phase 2 (one block per batch): 128 threads, 2 candidates per thread.
    // =======================================================================
    {
        const int nn0   = tid;          // candidate 0..127
        const int nn1   = tid + 128;    // candidate 128..255
        const int lane2 = tid & 31;
        const int w2    = tid >> 5;     // 0..3

        __shared__ float s_mn[4][4], s_mx[4][4];
        __shared__ float s_fmn[4], s_fmx[4];
        __shared__ float s_bs[4];
        __shared__ int   s_bi[4];
        __shared__ int   s_best;

        // L2-coherent reads of both candidates' raw scores
        const float4* sc0 = &g_scratch[b * Nc + nn0];
        const float4* sc1 = &g_scratch[b * Nc + nn1];
        float4 r0, r1;
        r0.x = __ldcg(&sc0->x); r0.y = __ldcg(&sc0->y);
        r0.z = __ldcg(&sc0->z); r0.w = __ldcg(&sc0->w);
        r1.x = __ldcg(&sc1->x); r1.y = __ldcg(&sc1->y);
        r1.z = __ldcg(&sc1->z); r1.w = __ldcg(&sc1->w);

        float t0v = sqrtf(r0.z) - COL_THRESH;
        float t1v = sqrtf(r1.z) - COL_THRESH;
        float v0[4] = {r0.x, r0.y, expf(-(t0v * t0v)), r0.w};
        float v1[4] = {r1.x, r1.y, expf(-(t1v * t1v)), r1.w};

        // --- combined min/max reduction over both local candidates ---
        float mn4[4], mx4[4];
#pragma unroll
        for (int i = 0; i < 4; i++) {
            mn4[i] = fminf(v0[i], v1[i]);
            mx4[i] = fmaxf(v0[i], v1[i]);
        }
#pragma unroll
        for (int off = 16; off > 0; off >>= 1) {
#pragma unroll
            for (int i = 0; i < 4; i++) {
                mn4[i] = fminf(mn4[i], __shfl_xor_sync(0xFFFFFFFFu, mn4[i], off));
                mx4[i] = fmaxf(mx4[i], __shfl_xor_sync(0xFFFFFFFFu, mx4[i], off));
            }
        }
        if (lane2 == 0) {
#pragma unroll
            for (int i = 0; i < 4; i++) { s_mn[w2][i] = mn4[i]; s_mx[w2][i] = mx4[i]; }
        }
        __syncthreads();
        if (w2 == 0) {   // full warp participates — convergent shuffles
#pragma unroll
            for (int i = 0; i < 4; i++) {
                mn4[i] = s_mn[lane2 & 3][i];
                mx4[i] = s_mx[lane2 & 3][i];
            }
#pragma unroll
            for (int off = 2; off > 0; off >>= 1) {
#pragma unroll
                for (int i = 0; i < 4; i++) {
                    mn4[i] = fminf(mn4[i], __shfl_xor_sync(0xFFFFFFFFu, mn4[i], off));
                    mx4[i] = fmaxf(mx4[i], __shfl_xor_sync(0xFFFFFFFFu, mx4[i], off));
                }
            }
            if (lane2 == 0) {
#pragma unroll
                for (int i = 0; i < 4; i++) { s_fmn[i] = mn4[i]; s_fmx[i] = mx4[i]; }
            }
        }
        __syncthreads();

        float score0 = 0.0f, score1 = 0.0f;
#pragma unroll
        for (int i = 0; i < 4; i++) {
            float d = s_fmx[i] - s_fmn[i];
            d = (d == 0.0f) ? 1.0f : d;
            score0 += (v0[i] - s_fmn[i]) / d;
            score1 += (v1[i] - s_fmn[i]) / d;
        }
        score0 = -score0;
        score1 = -score1;

        // scores output region follows the best_trajectory block
        float* out_scores = out + (Bc * Tc * 2);
        out_scores[b * Nc + nn0] = score0;
        out_scores[b * Nc + nn1] = score1;

        // --- argmax with first-index tie-break (matches jnp.argmax) ---
        // local combine: nn0 < nn1, so strict > keeps the first index on tie
        float bs = score0;
        int   bi = nn0;
        if (score1 > bs) { bs = score1; bi = nn1; }
#pragma unroll
        for (int off = 16; off > 0; off >>= 1) {
            float os = __shfl_xor_sync(0xFFFFFFFFu, bs, off);
            int   oi = __shfl_xor_sync(0xFFFFFFFFu, bi, off);
            if (os > bs || (os == bs && oi < bi)) { bs = os; bi = oi; }
        }
        if (lane2 == 0) { s_bs[w2] = bs; s_bi[w2] = bi; }
        __syncthreads();
        if (w2 == 0) {   // full warp participates — convergent shuffles
            bs = s_bs[lane2 & 3];
            bi = s_bi[lane2 & 3];
#pragma unroll
            for (int off = 2; off > 0; off >>= 1) {
                float os = __shfl_xor_sync(0xFFFFFFFFu, bs, off);
                int   oi = __shfl_xor_sync(0xFFFFFFFFu, bi, off);
                if (os > bs || (os == bs && oi < bi)) { bs = os; bi = oi; }
            }
            if (lane2 == 0) s_best = bi;
        }
        __syncthreads();

        // --- copy best trajectory: T*2 = 128 floats = 64 float2 ---
        const int best = s_best;
        if (tid < Tc) {
            ((float2*)out)[b * Tc + tid] =
                ((const float2*)traj)[((size_t)(b * Nc + best)) * Tc + tid];
        }

        // reset counter for the next graph replay (all arrivals already in)
        if (tid == 0) g_cnt[b] = 0;
    }
}

// ---------------------------------------------------------------------------
// Launch
// ---------------------------------------------------------------------------
extern "C" void kernel_launch(void* const* d_in, const int* in_sizes, int n_in,
                              void* d_out, int out_size)
{
    const float* traj = (const float*)d_in[0];   // (B,N,T,2)
    const float* goal = (const float*)d_in[1];   // (B,2)
    const float* gt   = (const float*)d_in[2];   // (B,T,2)
    const float* obs  = (const float*)d_in[3];   // (B,M,2)
    const float* da   = (const float*)d_in[4];   // (B,H,W)
    float* out = (float*)d_out;

    dim3 g1(BLKS_PER_B, Bc);
    fused_kernel<<<g1, THREADS>>>(traj, goal, gt, obs, da, out);
}

// round 14
// speedup vs baseline: 1.2607x; 1.0156x over previous
#include <cuda_runtime.h>
#include <math.h>

// Problem constants
#define Bc 32
#define Nc 256
#define Tc 64
#define Mc 64
#define Hc 512
#define Wc 512
#define COL_THRESH 0.5f

#define GRP 8                       // threads per candidate
#define T_PER_THR 8                 // timesteps per thread (GRP*T_PER_THR = Tc)
#define CAND_PER_BLK 16             // candidates per 128-thread block
#define THREADS 128
#define BLKS_PER_B (Nc / CAND_PER_BLK)   // 16 blocks per batch -> 512 blocks

// Scratch for raw per-(b,n) scores: [f_dis, f_pg, min_col_sq, f_dac]
__device__ float4 g_scratch[Bc * Nc];
// Per-batch completion counters (zero-initialized; reset by the winner)
__device__ int g_cnt[Bc];

// ---------------------------------------------------------------------------
// Fused kernel. grid = (16, B), block = 128 threads — 512 blocks, one wave.
// Phase 0: warm this batch's drivable-area slice into L2 with coalesced
//          streaming loads (one float per 32B sector) so the random DAC
//          gathers below become L2 hits instead of random DRAM sectors.
// Phase 1: 8-thread groups compute raw scores, 8 timesteps per thread.
// Phase 2: the LAST block per batch normalizes, argmaxes, copies best traj.
// ---------------------------------------------------------------------------
__global__ __launch_bounds__(THREADS) void fused_kernel(
    const float* __restrict__ traj,     // (B,N,T,2)
    const float* __restrict__ goal,     // (B,2)
    const float* __restrict__ gt,       // (B,T,2)
    const float* __restrict__ obs,      // (B,M,2)
    const float* __restrict__ da,       // (B,H,W)
    float* __restrict__ out)            // [B*T*2 best | B*N scores]
{
    const int b   = blockIdx.y;
    const int tid = threadIdx.x;
    const int c   = tid >> 3;                       // candidate slot 0..15
    const int tg  = tid & 7;                        // thread-in-group 0..7
    const int n   = blockIdx.x * CAND_PER_BLK + c;  // candidate index
    const int t0  = tg * T_PER_THR;                 // first timestep

    __shared__ float4 s_obs[Mc];   // (-2*ox, -2*oy, |o|^2, pad)
    __shared__ int    s_last;

    // ===== Phase 0: L2 warming of this block's 64KB slice of da[b] =====
    // Block x warms floats [x*16384, (x+1)*16384) of batch b's 256K-float map.
    // One float per 32B sector (stride 8 floats); warp lanes are consecutive
    // sectors, so each warp-load covers 1KB contiguously (streaming-friendly).
    {
        const float* wbase = da + (size_t)b * (Hc * Wc) + blockIdx.x * 16384;
        float wsum = 0.0f;
#pragma unroll
        for (int k = 0; k < 16; k++)
            wsum += __ldcg(wbase + (((k * THREADS) + tid) << 3));
        asm volatile("" :: "f"(wsum));   // keep the loads alive
    }

    // ===== FRONT-BATCHED LOADS =====

    // my 8 trajectory points (4x float4, coalesced)
    const float4* traj4 = (const float4*)traj;
    const int base4 = ((b * Nc + n) * Tc + t0) >> 1;
    float4 q0 = traj4[base4];
    float4 q1 = traj4[base4 + 1];
    float4 q2 = traj4[base4 + 2];
    float4 q3 = traj4[base4 + 3];

    // gt points (batch-broadcast, cached)
    const float4* gt4 = (const float4*)gt;
    const int gbase4 = (b * Tc + t0) >> 1;
    float4 G0 = __ldg(&gt4[gbase4]);
    float4 G1 = __ldg(&gt4[gbase4 + 1]);
    float4 G2 = __ldg(&gt4[gbase4 + 2]);
    float4 G3 = __ldg(&gt4[gbase4 + 3]);

    // goal (endpoint-owner only)
    float2 gl = make_float2(0.0f, 0.0f);
    if (tg == GRP - 1) gl = ((const float2*)goal)[b];

    // obstacle prefetch into registers (first 64 threads)
    float2 opre = make_float2(0.0f, 0.0f);
    if (tid < Mc) opre = ((const float2*)obs)[b * Mc + tid];

    // unpack points
    float px[8] = {q0.x, q0.z, q1.x, q1.z, q2.x, q2.z, q3.x, q3.z};
    float py[8] = {q0.y, q0.w, q1.y, q1.w, q2.y, q2.w, q3.y, q3.w};

    // ===== DAC gathers (mostly L2 hits thanks to warming) =====
    float dval[8];
#pragma unroll
    for (int j = 0; j < 8; j++) {
        int xi = (int)((px[j] + 50.0f) / 100.0f * (float)(Wc - 1));
        int yi = (int)((py[j] + 50.0f) / 100.0f * (float)(Hc - 1));
        xi = min(max(xi, 0), Wc - 1);
        yi = min(max(yi, 0), Hc - 1);
        dval[j] = __ldg(&da[(size_t)b * (Hc * Wc) + yi * Wc + xi]);
    }

    // stage transformed obstacles into shared
    if (tid < Mc) {
        float o2 = fmaf(opre.x, opre.x, opre.y * opre.y);
        s_obs[tid] = make_float4(-2.0f * opre.x, -2.0f * opre.y, o2, 0.0f);
    }

    // --- distance-to-GT while the STS drains ---
    float gx[8] = {G0.x, G0.z, G1.x, G1.z, G2.x, G2.z, G3.x, G3.z};
    float gy[8] = {G0.y, G0.w, G1.y, G1.w, G2.y, G2.w, G3.y, G3.w};
    float dis = 0.0f;
#pragma unroll
    for (int j = 0; j < 8; j++) {
        float dx = px[j] - gx[j], dy = py[j] - gy[j];
        dis += sqrtf(fmaf(dx, dx, dy * dy));
    }

    // --- progress term (endpoint owner only) ---
    float pg = 0.0f;
    if (tg == GRP - 1) {
        float ex = px[7] - gl.x, ey = py[7] - gl.y;
        pg = sqrtf(fmaf(ex, ex, ey * ey));
    }

    __syncthreads();   // obstacles visible

    // --- collision: min over M of (|o|^2 - 2 p.o) per point; 1 LDS / 8 pts ---
    const float BIG = 3.402823466e+38f;
    float mc[8] = {BIG, BIG, BIG, BIG, BIG, BIG, BIG, BIG};
#pragma unroll 4
    for (int m = 0; m < Mc; m++) {
        float4 o = s_obs[m];       // broadcast, conflict-free
#pragma unroll
        for (int j = 0; j < 8; j++)
            mc[j] = fminf(mc[j], fmaf(py[j], o.y, fmaf(px[j], o.x, o.z)));
    }
    float mind2 = BIG;
#pragma unroll
    for (int j = 0; j < 8; j++)
        mind2 = fminf(mind2, fmaf(px[j], px[j], py[j] * py[j]) + mc[j]);
    mind2 = fmaxf(mind2, 0.0f);    // clamp commutes with min; guard sqrt later

    // --- consume DAC gathers ---
    float dac = 0.0f;
#pragma unroll
    for (int j = 0; j < 8; j++) dac += 1.0f - dval[j];

    // --- 8-lane group reduction (xor offsets stay inside the group) ---
#pragma unroll
    for (int off = 4; off > 0; off >>= 1) {
        dis   += __shfl_xor_sync(0xFFFFFFFFu, dis, off);
        dac   += __shfl_xor_sync(0xFFFFFFFFu, dac, off);
        pg    += __shfl_xor_sync(0xFFFFFFFFu, pg, off);
        mind2  = fminf(mind2, __shfl_xor_sync(0xFFFFFFFFu, mind2, off));
    }
    if (tg == 0) {
        g_scratch[b * Nc + n] =
            make_float4(dis * (1.0f / Tc), pg, mind2, dac * (1.0f / Tc));
        __threadfence();   // storer fences its own write before block signal
    }
    __syncthreads();

    // ---- completion signalling: last block for this batch does the select ---
    if (tid == 0) {
        int old = atomicAdd(&g_cnt[b], 1);
        s_last = (old == BLKS_PER_B - 1) ? 1 : 0;
    }
    __syncthreads();
    if (!s_last) return;
    __threadfence();                          // acquire others' scratch writes

    // =======================================================================
    // Phase 2 (one block per batch): 128 threads, 2 candidates per thread.
    // =======================================================================
    {
        const int nn0   = tid;          // candidate 0..127
        const int nn1   = tid + 128;    // candidate 128..255
        const int lane2 = tid & 31;
        const int w2    = tid >> 5;     // 0..3

        __shared__ float s_mn[4][4], s_mx[4][4];
        __shared__ float s_fmn[4], s_fmx[4];
        __shared__ float s_bs[4];
        __shared__ int   s_bi[4];
        __shared__ int   s_best;

        // L2-coherent reads of both candidates' raw scores
        const float4* sc0 = &g_scratch[b * Nc + nn0];
        const float4* sc1 = &g_scratch[b * Nc + nn1];
        float4 r0, r1;
        r0.x = __ldcg(&sc0->x); r0.y = __ldcg(&sc0->y);
        r0.z = __ldcg(&sc0->z); r0.w = __ldcg(&sc0->w);
        r1.x = __ldcg(&sc1->x); r1.y = __ldcg(&sc1->y);
        r1.z = __ldcg(&sc1->z); r1.w = __ldcg(&sc1->w);

        float t0v = sqrtf(r0.z) - COL_THRESH;
        float t1v = sqrtf(r1.z) - COL_THRESH;
        float v0[4] = {r0.x, r0.y, expf(-(t0v * t0v)), r0.w};
        float v1[4] = {r1.x, r1.y, expf(-(t1v * t1v)), r1.w};

        // --- combined min/max reduction over both local candidates ---
        float mn4[4], mx4[4];
#pragma unroll
        for (int i = 0; i < 4; i++) {
            mn4[i] = fminf(v0[i], v1[i]);
            mx4[i] = fmaxf(v0[i], v1[i]);
        }
#pragma unroll
        for (int off = 16; off > 0; off >>= 1) {
#pragma unroll
            for (int i = 0; i < 4; i++) {
                mn4[i] = fminf(mn4[i], __shfl_xor_sync(0xFFFFFFFFu, mn4[i], off));
                mx4[i] = fmaxf(mx4[i], __shfl_xor_sync(0xFFFFFFFFu, mx4[i], off));
            }
        }
        if (lane2 == 0) {
#pragma unroll
            for (int i = 0; i < 4; i++) { s_mn[w2][i] = mn4[i]; s_mx[w2][i] = mx4[i]; }
        }
        __syncthreads();
        if (w2 == 0) {   // full warp participates — convergent shuffles
#pragma unroll
            for (int i = 0; i < 4; i++) {
                mn4[i] = s_mn[lane2 & 3][i];
                mx4[i] = s_mx[lane2 & 3][i];
            }
#pragma unroll
            for (int off = 2; off > 0; off >>= 1) {
#pragma unroll
                for (int i = 0; i < 4; i++) {
                    mn4[i] = fminf(mn4[i], __shfl_xor_sync(0xFFFFFFFFu, mn4[i], off));
                    mx4[i] = fmaxf(mx4[i], __shfl_xor_sync(0xFFFFFFFFu, mx4[i], off));
                }
            }
            if (lane2 == 0) {
#pragma unroll
                for (int i = 0; i < 4; i++) { s_fmn[i] = mn4[i]; s_fmx[i] = mx4[i]; }
            }
        }
        __syncthreads();

        float score0 = 0.0f, score1 = 0.0f;
#pragma unroll
        for (int i = 0; i < 4; i++) {
            float d = s_fmx[i] - s_fmn[i];
            d = (d == 0.0f) ? 1.0f : d;
            score0 += (v0[i] - s_fmn[i]) / d;
            score1 += (v1[i] - s_fmn[i]) / d;
        }
        score0 = -score0;
        score1 = -score1;

        // scores output region follows the best_trajectory block
        float* out_scores = out + (Bc * Tc * 2);
        out_scores[b * Nc + nn0] = score0;
        out_scores[b * Nc + nn1] = score1;

        // --- argmax with first-index tie-break (matches jnp.argmax) ---
        float bs = score0;
        int   bi = nn0;
        if (score1 > bs) { bs = score1; bi = nn1; }
#pragma unroll
        for (int off = 16; off > 0; off >>= 1) {
            float os = __shfl_xor_sync(0xFFFFFFFFu, bs, off);
            int   oi = __shfl_xor_sync(0xFFFFFFFFu, bi, off);
            if (os > bs || (os == bs && oi < bi)) { bs = os; bi = oi; }
        }
        if (lane2 == 0) { s_bs[w2] = bs; s_bi[w2] = bi; }
        __syncthreads();
        if (w2 == 0) {   // full warp participates — convergent shuffles
            bs = s_bs[lane2 & 3];
            bi = s_bi[lane2 & 3];
#pragma unroll
            for (int off = 2; off > 0; off >>= 1) {
                float os = __shfl_xor_sync(0xFFFFFFFFu, bs, off);
                int   oi = __shfl_xor_sync(0xFFFFFFFFu, bi, off);
                if (os > bs || (os == bs && oi < bi)) { bs = os; bi = oi; }
            }
            if (lane2 == 0) s_best = bi;
        }
        __syncthreads();

        // --- copy best trajectory: T*2 = 128 floats = 64 float2 ---
        const int best = s_best;
        if (tid < Tc) {
            ((float2*)out)[b * Tc + tid] =
                ((const float2*)traj)[((size_t)(b * Nc + best)) * Tc + tid];
        }

        // reset counter for the next graph replay (all arrivals already in)
        if (tid == 0) g_cnt[b] = 0;
    }
}

// ---------------------------------------------------------------------------
// Launch
// ---------------------------------------------------------------------------
extern "C" void kernel_launch(void* const* d_in, const int* in_sizes, int n_in,
                              void* d_out, int out_size)
{
    const float* traj = (const float*)d_in[0];   // (B,N,T,2)
    const float* goal = (const float*)d_in[1];   // (B,2)
    const float* gt   = (const float*)d_in[2];   // (B,T,2)
    const float* obs  = (const float*)d_in[3];   // (B,M,2)
    const float* da   = (const float*)d_in[4];   // (B,H,W)
    float* out = (float*)d_out;

    dim3 g1(BLKS_PER_B, Bc);
    fused_kernel<<<g1, THREADS>>>(traj, goal, gt, obs, da, out);
}